// round 5
// baseline (speedup 1.0000x reference)
#include <cuda_runtime.h>
#include <cstdint>

#define NB    16
#define NPTS  4096
#define SPTS  1024
#define COLS  65536
#define JCOLS 16384

__device__ __align__(16) float g_Z[3u * 16384u * 256u];
__device__ __align__(16) float g_Y[256u * 65536u];
__device__ __align__(16) float g_O2[128u * 65536u];
__device__ __align__(16) float g_W0T[512 * 256];
__device__ __align__(16) float g_W1T[256 * 128];
__device__ int   g_idx[65536 * 3];
__device__ float g_w[65536 * 3];
__device__ float g_sum0[256], g_sq0[256], g_a0[256], g_c0[256];
__device__ float g_sum1[128], g_sq1[128], g_a1[128], g_c1[128];

__device__ __forceinline__ void cp16(uint32_t dst, const void* src) {
    asm volatile("cp.async.ca.shared.global [%0], [%1], 16;\n" :: "r"(dst), "l"(src));
}
__device__ __forceinline__ void cp_commit() { asm volatile("cp.async.commit_group;\n"); }
template<int N> __device__ __forceinline__ void cp_wait() {
    asm volatile("cp.async.wait_group %0;\n" :: "n"(N));
}

// Packed fp32x2 helpers (FFMA2 — only reachable via PTX)
__device__ __forceinline__ unsigned long long pack2(float a, float b) {
    unsigned long long r;
    asm("mov.b64 %0, {%1, %2};" : "=l"(r) : "f"(a), "f"(b));
    return r;
}
__device__ __forceinline__ void fma2(unsigned long long& d, unsigned long long a,
                                     unsigned long long b) {
    asm("fma.rn.f32x2 %0, %1, %2, %3;" : "=l"(d) : "l"(a), "l"(b), "l"(d));
}
__device__ __forceinline__ void unpack2(unsigned long long v, float& lo, float& hi) {
    asm("mov.b64 {%0, %1}, %2;" : "=f"(lo), "=f"(hi) : "l"(v));
}

// ---------------- prep: zero stats + transpose weights ----------------
__global__ void prep_kernel(const float* __restrict__ w0, const float* __restrict__ w1) {
    const int idx = blockIdx.x * 256 + threadIdx.x;
    if (idx < 256) { g_sum0[idx] = 0.f; g_sq0[idx] = 0.f; }
    if (idx < 128) { g_sum1[idx] = 0.f; g_sq1[idx] = 0.f; }
    if (idx < 512 * 256) g_W0T[idx] = w0[(idx & 255) * 512 + (idx >> 8)];
    if (idx < 256 * 128) g_W1T[idx] = w1[(idx & 127) * 256 + (idx >> 7)];
}

// ---------------- 3-NN search + interpolation weights ----------------
__global__ void knn_kernel(const float* __restrict__ xyz1,
                           const float* __restrict__ xyz2) {
    __shared__ float sx[SPTS], sy[SPTS], sz[SPTS], sn[SPTS];
    const int t = threadIdx.x;
    const int b = blockIdx.x >> 4;
    const int qbase = (blockIdx.x & 15) << 8;
    const float* base2 = xyz2 + (size_t)b * 3 * SPTS;
    for (int i = t; i < SPTS; i += 256) {
        float x = base2[i], y = base2[SPTS + i], z = base2[2 * SPTS + i];
        sx[i] = x; sy[i] = y; sz[i] = z; sn[i] = x * x + y * y + z * z;
    }
    __syncthreads();
    const int n = qbase + t;
    const float* base1 = xyz1 + (size_t)b * 3 * NPTS;
    const float qx = base1[n], qy = base1[NPTS + n], qz = base1[2 * NPTS + n];
    const float qn = qx * qx + qy * qy + qz * qz;
    float d0 = 3.4e38f, d1 = 3.4e38f, d2 = 3.4e38f;
    int i0 = 0, i1 = 0, i2 = 0;
#pragma unroll 4
    for (int s = 0; s < SPTS; s++) {
        float d = qn + sn[s] - 2.f * (qx * sx[s] + qy * sy[s] + qz * sz[s]);
        if (d < d2) {
            if (d < d1) {
                if (d < d0) { d2 = d1; i2 = i1; d1 = d0; i1 = i0; d0 = d; i0 = s; }
                else        { d2 = d1; i2 = i1; d1 = d;  i1 = s; }
            } else          { d2 = d;  i2 = s; }
        }
    }
    const float r0 = 1.f / (d0 + 1e-8f);
    const float r1 = 1.f / (d1 + 1e-8f);
    const float r2 = 1.f / (d2 + 1e-8f);
    const float inv = 1.f / (r0 + r1 + r2);
    const int col = b * NPTS + n;
    g_idx[col * 3 + 0] = i0; g_idx[col * 3 + 1] = i1; g_idx[col * 3 + 2] = i2;
    g_w[col * 3 + 0] = r0 * inv; g_w[col * 3 + 1] = r1 * inv; g_w[col * 3 + 2] = r2 * inv;
}

// ---------------- GEMM Z: M=768 (k,o), K=128, cols=16384 ----------------
__global__ __launch_bounds__(256, 2) void gemmZ(const float* __restrict__ p2) {
    __shared__ __align__(16) float As[3][8][128];
    __shared__ __align__(16) float Bs[3][8][128];
    const int t = threadIdx.x;
    const int tx = t & 15, ty = t >> 4;
    const int col0 = blockIdx.x * 128;
    const int kg = blockIdx.y >> 1;
    const int o0 = (blockIdx.y & 1) * 128;
    const int bb = col0 >> 10, sOff = col0 & 1023;
    const int lk = t >> 5, lc = (t & 31) * 4;
    const float* aSrc = g_W0T + (size_t)(128 + kg * 128 + lk) * 256 + o0 + lc;
    const float* bSrc = p2 + ((size_t)bb * 128 + lk) * 1024 + sOff + lc;
    const uint32_t aDst = (uint32_t)__cvta_generic_to_shared(&As[0][lk][lc]);
    const uint32_t bDst = (uint32_t)__cvta_generic_to_shared(&Bs[0][lk][lc]);
    const uint32_t SB = 8 * 128 * 4;

    unsigned long long acc2[8][4];
#pragma unroll
    for (int i = 0; i < 8; i++)
#pragma unroll
        for (int j = 0; j < 4; j++) acc2[i][j] = 0ull;

    cp16(aDst, aSrc); cp16(bDst, bSrc); cp_commit();
    cp16(aDst + SB, aSrc + 8 * 256); cp16(bDst + SB, bSrc + 8 * 1024); cp_commit();

    int ls = 2, cs = 0;
#pragma unroll 1
    for (int kt = 0; kt < 16; kt++) {
        cp_wait<1>();
        __syncthreads();
        if (kt + 2 < 16) {
            cp16(aDst + ls * SB, aSrc + (size_t)(kt + 2) * 8 * 256);
            cp16(bDst + ls * SB, bSrc + (size_t)(kt + 2) * 8 * 1024);
        }
        cp_commit();
        ls++; if (ls == 3) ls = 0;
#pragma unroll
        for (int kk = 0; kk < 8; kk++) {
            float ar[8];
            *(float4*)&ar[0] = *(const float4*)&As[cs][kk][ty * 8];
            *(float4*)&ar[4] = *(const float4*)&As[cs][kk][ty * 8 + 4];
            ulonglong2 u0 = *(const ulonglong2*)&Bs[cs][kk][tx * 8];
            ulonglong2 u1 = *(const ulonglong2*)&Bs[cs][kk][tx * 8 + 4];
            unsigned long long br2[4] = {u0.x, u0.y, u1.x, u1.y};
#pragma unroll
            for (int i = 0; i < 8; i++) {
                const unsigned long long ai = pack2(ar[i], ar[i]);
#pragma unroll
                for (int j = 0; j < 4; j++) fma2(acc2[i][j], ai, br2[j]);
            }
        }
        cs++; if (cs == 3) cs = 0;
    }
    float acc[8][8];
#pragma unroll
    for (int i = 0; i < 8; i++)
#pragma unroll
        for (int j = 0; j < 4; j++) unpack2(acc2[i][j], acc[i][2 * j], acc[i][2 * j + 1]);

    const int obase = o0 + ty * 8;
#pragma unroll
    for (int j = 0; j < 8; j++) {
        const int col = col0 + tx * 8 + j;
        float* zp = g_Z + ((size_t)(kg * JCOLS + col)) * 256 + obase;
        *(float4*)zp       = make_float4(acc[0][j], acc[1][j], acc[2][j], acc[3][j]);
        *(float4*)(zp + 4) = make_float4(acc[4][j], acc[5][j], acc[6][j], acc[7][j]);
    }
}

// ---------------- GEMM Y: M=256, K=128, cols=65536; gather + stats epilogue ----------------
__global__ __launch_bounds__(256, 2) void gemmY(const float* __restrict__ p1,
                                                const float* __restrict__ bias0) {
    __shared__ __align__(16) float As[3][8][128];
    __shared__ __align__(16) float Bs[3][8][128];
    const int t = threadIdx.x;
    const int tx = t & 15, ty = t >> 4;
    const int col0 = blockIdx.x * 128;
    const int m0 = blockIdx.y * 128;
    const int bb = col0 >> 12, nOff = col0 & 4095;
    const int lk = t >> 5, lc = (t & 31) * 4;
    const float* aSrc = g_W0T + (size_t)lk * 256 + m0 + lc;
    const float* bSrc = p1 + ((size_t)bb * 128 + lk) * 4096 + nOff + lc;
    const uint32_t aDst = (uint32_t)__cvta_generic_to_shared(&As[0][lk][lc]);
    const uint32_t bDst = (uint32_t)__cvta_generic_to_shared(&Bs[0][lk][lc]);
    const uint32_t SB = 8 * 128 * 4;

    unsigned long long acc2[8][4];
#pragma unroll
    for (int i = 0; i < 8; i++)
#pragma unroll
        for (int j = 0; j < 4; j++) acc2[i][j] = 0ull;

    cp16(aDst, aSrc); cp16(bDst, bSrc); cp_commit();
    cp16(aDst + SB, aSrc + 8 * 256); cp16(bDst + SB, bSrc + 8 * 4096); cp_commit();

    int ls = 2, cs = 0;
#pragma unroll 1
    for (int kt = 0; kt < 16; kt++) {
        cp_wait<1>();
        __syncthreads();
        if (kt + 2 < 16) {
            cp16(aDst + ls * SB, aSrc + (size_t)(kt + 2) * 8 * 256);
            cp16(bDst + ls * SB, bSrc + (size_t)(kt + 2) * 8 * 4096);
        }
        cp_commit();
        ls++; if (ls == 3) ls = 0;
#pragma unroll
        for (int kk = 0; kk < 8; kk++) {
            float ar[8];
            *(float4*)&ar[0] = *(const float4*)&As[cs][kk][ty * 8];
            *(float4*)&ar[4] = *(const float4*)&As[cs][kk][ty * 8 + 4];
            ulonglong2 u0 = *(const ulonglong2*)&Bs[cs][kk][tx * 8];
            ulonglong2 u1 = *(const ulonglong2*)&Bs[cs][kk][tx * 8 + 4];
            unsigned long long br2[4] = {u0.x, u0.y, u1.x, u1.y};
#pragma unroll
            for (int i = 0; i < 8; i++) {
                const unsigned long long ai = pack2(ar[i], ar[i]);
#pragma unroll
                for (int j = 0; j < 4; j++) fma2(acc2[i][j], ai, br2[j]);
            }
        }
        cs++; if (cs == 3) cs = 0;
    }

    float acc[8][8];
#pragma unroll
    for (int i = 0; i < 8; i++)
#pragma unroll
        for (int j = 0; j < 4; j++) unpack2(acc2[i][j], acc[i][2 * j], acc[i][2 * j + 1]);

    const int rowb = m0 + ty * 8;
    float bias[8];
#pragma unroll
    for (int i = 0; i < 8; i++) bias[i] = bias0[rowb + i];

#pragma unroll
    for (int j = 0; j < 8; j++) {
        const int col = col0 + tx * 8 + j;
        const int ia = g_idx[col * 3], ib = g_idx[col * 3 + 1], ic = g_idx[col * 3 + 2];
        const float wa = g_w[col * 3], wb = g_w[col * 3 + 1], wc = g_w[col * 3 + 2];
        const int jb = (col >> 12) << 10;
        const float* z0 = g_Z + ((size_t)(jb + ia)) * 256 + rowb;
        const float* z1 = g_Z + ((size_t)(JCOLS + jb + ib)) * 256 + rowb;
        const float* z2 = g_Z + ((size_t)(2 * JCOLS + jb + ic)) * 256 + rowb;
        float4 p0 = *(const float4*)z0, p0b = *(const float4*)(z0 + 4);
        float4 q0 = *(const float4*)z1, q0b = *(const float4*)(z1 + 4);
        float4 r0 = *(const float4*)z2, r0b = *(const float4*)(z2 + 4);
        acc[0][j] += bias[0] + wa * p0.x  + wb * q0.x  + wc * r0.x;
        acc[1][j] += bias[1] + wa * p0.y  + wb * q0.y  + wc * r0.y;
        acc[2][j] += bias[2] + wa * p0.z  + wb * q0.z  + wc * r0.z;
        acc[3][j] += bias[3] + wa * p0.w  + wb * q0.w  + wc * r0.w;
        acc[4][j] += bias[4] + wa * p0b.x + wb * q0b.x + wc * r0b.x;
        acc[5][j] += bias[5] + wa * p0b.y + wb * q0b.y + wc * r0b.y;
        acc[6][j] += bias[6] + wa * p0b.z + wb * q0b.z + wc * r0b.z;
        acc[7][j] += bias[7] + wa * p0b.w + wb * q0b.w + wc * r0b.w;
    }

    const int colT = col0 + tx * 8;
#pragma unroll
    for (int i = 0; i < 8; i++) {
        const int row = rowb + i;
        float* yp = g_Y + (size_t)row * COLS + colT;
        *(float4*)yp       = make_float4(acc[i][0], acc[i][1], acc[i][2], acc[i][3]);
        *(float4*)(yp + 4) = make_float4(acc[i][4], acc[i][5], acc[i][6], acc[i][7]);
        float s = 0.f, q = 0.f;
#pragma unroll
        for (int j = 0; j < 8; j++) { s += acc[i][j]; q += acc[i][j] * acc[i][j]; }
#pragma unroll
        for (int off = 8; off; off >>= 1) {
            s += __shfl_xor_sync(0xffffffffu, s, off);
            q += __shfl_xor_sync(0xffffffffu, q, off);
        }
        if ((t & 15) == 0) { atomicAdd(&g_sum0[row], s); atomicAdd(&g_sq0[row], q); }
    }
}

__global__ void finalize0(const float* __restrict__ gamma, const float* __restrict__ beta) {
    const int t = threadIdx.x;
    const float mean = g_sum0[t] * (1.f / COLS);
    const float var = g_sq0[t] * (1.f / COLS) - mean * mean;
    const float a = gamma[t] * rsqrtf(var + 1e-5f);
    g_a0[t] = a;
    g_c0[t] = beta[t] - mean * a;
}

// ---------------- GEMM O2: M=128, K=256, cols=65536; BN0+ReLU on B; stats ----------------
__global__ __launch_bounds__(256, 2) void gemmO2(const float* __restrict__ bias1) {
    __shared__ __align__(16) float As[3][8][128];
    __shared__ __align__(16) float Bs[3][8][128];
    __shared__ float s_a0[256], s_c0[256];
    const int t = threadIdx.x;
    const int tx = t & 15, ty = t >> 4;
    const int col0 = blockIdx.x * 128;
    const int lk = t >> 5, lc = (t & 31) * 4;
    s_a0[t] = g_a0[t];
    s_c0[t] = g_c0[t];
    const float* aSrc = g_W1T + (size_t)lk * 128 + lc;
    const float* bSrc = g_Y + (size_t)lk * COLS + col0 + lc;
    const uint32_t aDst = (uint32_t)__cvta_generic_to_shared(&As[0][lk][lc]);
    const uint32_t bDst = (uint32_t)__cvta_generic_to_shared(&Bs[0][lk][lc]);
    const uint32_t SB = 8 * 128 * 4;

    unsigned long long acc2[8][4];
#pragma unroll
    for (int i = 0; i < 8; i++)
#pragma unroll
        for (int j = 0; j < 4; j++) acc2[i][j] = 0ull;

    cp16(aDst, aSrc); cp16(bDst, bSrc); cp_commit();
    cp16(aDst + SB, aSrc + 8 * 128); cp16(bDst + SB, bSrc + (size_t)8 * COLS); cp_commit();

    int ls = 2, cs = 0;
#pragma unroll 1
    for (int kt = 0; kt < 32; kt++) {
        cp_wait<1>();
        __syncthreads();
        if (kt + 2 < 32) {
            cp16(aDst + ls * SB, aSrc + (size_t)(kt + 2) * 8 * 128);
            cp16(bDst + ls * SB, bSrc + (size_t)(kt + 2) * 8 * COLS);
        }
        cp_commit();
        ls++; if (ls == 3) ls = 0;
#pragma unroll
        for (int kk = 0; kk < 8; kk++) {
            const float sa = s_a0[kt * 8 + kk];
            const float sc = s_c0[kt * 8 + kk];
            float ar[8], br[8];
            *(float4*)&ar[0] = *(const float4*)&As[cs][kk][ty * 8];
            *(float4*)&ar[4] = *(const float4*)&As[cs][kk][ty * 8 + 4];
            *(float4*)&br[0] = *(const float4*)&Bs[cs][kk][tx * 8];
            *(float4*)&br[4] = *(const float4*)&Bs[cs][kk][tx * 8 + 4];
#pragma unroll
            for (int j = 0; j < 8; j++) br[j] = fmaxf(0.f, fmaf(sa, br[j], sc));
            unsigned long long br2[4];
#pragma unroll
            for (int j = 0; j < 4; j++) br2[j] = pack2(br[2 * j], br[2 * j + 1]);
#pragma unroll
            for (int i = 0; i < 8; i++) {
                const unsigned long long ai = pack2(ar[i], ar[i]);
#pragma unroll
                for (int j = 0; j < 4; j++) fma2(acc2[i][j], ai, br2[j]);
            }
        }
        cs++; if (cs == 3) cs = 0;
    }

    float acc[8][8];
#pragma unroll
    for (int i = 0; i < 8; i++)
#pragma unroll
        for (int j = 0; j < 4; j++) unpack2(acc2[i][j], acc[i][2 * j], acc[i][2 * j + 1]);

    const int rowb = ty * 8;
    const int colT = col0 + tx * 8;
#pragma unroll
    for (int i = 0; i < 8; i++) {
        const int row = rowb + i;
        const float bias = bias1[row];
#pragma unroll
        for (int j = 0; j < 8; j++) acc[i][j] += bias;
        float* op = g_O2 + (size_t)row * COLS + colT;
        *(float4*)op       = make_float4(acc[i][0], acc[i][1], acc[i][2], acc[i][3]);
        *(float4*)(op + 4) = make_float4(acc[i][4], acc[i][5], acc[i][6], acc[i][7]);
        float s = 0.f, q = 0.f;
#pragma unroll
        for (int j = 0; j < 8; j++) { s += acc[i][j]; q += acc[i][j] * acc[i][j]; }
#pragma unroll
        for (int off = 8; off; off >>= 1) {
            s += __shfl_xor_sync(0xffffffffu, s, off);
            q += __shfl_xor_sync(0xffffffffu, q, off);
        }
        if ((t & 15) == 0) { atomicAdd(&g_sum1[row], s); atomicAdd(&g_sq1[row], q); }
    }
}

__global__ void finalize1(const float* __restrict__ gamma, const float* __restrict__ beta) {
    const int t = threadIdx.x;
    const float mean = g_sum1[t] * (1.f / COLS);
    const float var = g_sq1[t] * (1.f / COLS) - mean * mean;
    const float a = gamma[t] * rsqrtf(var + 1e-5f);
    g_a1[t] = a;
    g_c1[t] = beta[t] - mean * a;
}

// ---------------- BN2 + ReLU + transpose store ----------------
__global__ void bnout_kernel(float* __restrict__ out) {
    const int idx = blockIdx.x * 256 + threadIdx.x;
    const int e = idx * 4;
    const int row = e >> 16;
    const int col = e & 65535;
    const int b = col >> 12, n = col & 4095;
    float4 v = *(const float4*)&g_O2[(size_t)row * COLS + col];
    const float a = g_a1[row], c = g_c1[row];
    float4 w;
    w.x = fmaxf(0.f, fmaf(a, v.x, c));
    w.y = fmaxf(0.f, fmaf(a, v.y, c));
    w.z = fmaxf(0.f, fmaf(a, v.z, c));
    w.w = fmaxf(0.f, fmaf(a, v.w, c));
    *(float4*)&out[((size_t)(b * 128 + row)) * 4096 + n] = w;
}

extern "C" void kernel_launch(void* const* d_in, const int* in_sizes, int n_in,
                              void* d_out, int out_size) {
    const float* xyz1 = (const float*)d_in[0];
    const float* xyz2 = (const float*)d_in[1];
    const float* p1   = (const float*)d_in[2];
    const float* p2   = (const float*)d_in[3];
    const float* w0   = (const float*)d_in[4];
    const float* b0   = (const float*)d_in[5];
    const float* g0   = (const float*)d_in[6];
    const float* be0  = (const float*)d_in[7];
    const float* w1   = (const float*)d_in[8];
    const float* b1   = (const float*)d_in[9];
    const float* g1   = (const float*)d_in[10];
    const float* be1  = (const float*)d_in[11];
    float* out = (float*)d_out;

    prep_kernel<<<512, 256>>>(w0, w1);
    knn_kernel<<<256, 256>>>(xyz1, xyz2);
    gemmZ<<<dim3(JCOLS / 128, 6), 256>>>(p2);
    gemmY<<<dim3(COLS / 128, 2), 256>>>(p1, b0);
    finalize0<<<1, 256>>>(g0, be0);
    gemmO2<<<dim3(COLS / 128, 1), 256>>>(b1);
    finalize1<<<1, 128>>>(g1, be1);
    bnout_kernel<<<(COLS * 128 / 4) / 256, 256>>>(out);
}

// round 6
// speedup vs baseline: 1.3929x; 1.3929x over previous
#include <cuda_runtime.h>
#include <cuda_bf16.h>
#include <cstdint>

#define NB    16
#define NPTS  4096
#define SPTS  1024
#define COLS  65536
#define JCOLS 16384

// fp32 scratch
__device__ __align__(16) float g_Z[3u * 16384u * 256u];   // Z[k][col][o] o-contig
__device__ __align__(16) float g_Y[256u * 65536u];
__device__ __align__(16) float g_O2[128u * 65536u];
// bf16 split operands
__device__ __align__(16) __nv_bfloat16 g_W0Thi[512 * 256], g_W0Tlo[512 * 256];   // [c][o]
__device__ __align__(16) __nv_bfloat16 g_W1Thi[256 * 128], g_W1Tlo[256 * 128];   // [c][o]
__device__ __align__(16) __nv_bfloat16 g_P1hi[128u * 65536u], g_P1lo[128u * 65536u]; // [c][b*N+n]
__device__ __align__(16) __nv_bfloat16 g_P2hi[128u * 16384u], g_P2lo[128u * 16384u]; // [c][b*S+s]
__device__ __align__(16) __nv_bfloat16 g_Hhi[256u * 65536u], g_Hlo[256u * 65536u];   // relu(bn(Y))
__device__ int   g_idx[65536 * 3];
__device__ float g_w[65536 * 3];
__device__ float g_sum0[256], g_sq0[256], g_a0[256], g_c0[256];
__device__ float g_sum1[128], g_sq1[128], g_a1[128], g_c1[128];

__device__ __forceinline__ void cp16(uint32_t dst, const void* src) {
    asm volatile("cp.async.ca.shared.global [%0], [%1], 16;\n" :: "r"(dst), "l"(src));
}
__device__ __forceinline__ void cp_commit() { asm volatile("cp.async.commit_group;\n"); }
template<int N> __device__ __forceinline__ void cp_wait() {
    asm volatile("cp.async.wait_group %0;\n" :: "n"(N));
}

__device__ __forceinline__ void ldsm4t(uint32_t* r, uint32_t addr) {
    asm volatile("ldmatrix.sync.aligned.m8n8.x4.trans.shared.b16 {%0,%1,%2,%3}, [%4];"
                 : "=r"(r[0]), "=r"(r[1]), "=r"(r[2]), "=r"(r[3]) : "r"(addr));
}
__device__ __forceinline__ void ldsm2t(uint32_t* r, uint32_t addr) {
    asm volatile("ldmatrix.sync.aligned.m8n8.x2.trans.shared.b16 {%0,%1}, [%2];"
                 : "=r"(r[0]), "=r"(r[1]) : "r"(addr));
}
__device__ __forceinline__ void mma16816(float* d, const uint32_t* a, const uint32_t* b) {
    asm volatile("mma.sync.aligned.m16n8k16.row.col.f32.bf16.bf16.f32 "
                 "{%0,%1,%2,%3}, {%4,%5,%6,%7}, {%8,%9}, {%0,%1,%2,%3};"
                 : "+f"(d[0]), "+f"(d[1]), "+f"(d[2]), "+f"(d[3])
                 : "r"(a[0]), "r"(a[1]), "r"(a[2]), "r"(a[3]), "r"(b[0]), "r"(b[1]));
}

// smem stage layout (bytes): Ahi 8K | Alo 8K | Bhi 8K | Blo 8K ; 3 stages = 96KB
#define OFF_A_HI 0
#define OFF_A_LO 8192
#define OFF_B_HI 16384
#define OFF_B_LO 24576
#define STAGE    32768
#define SMEM_BYTES 98304

// one k16 compute step (all warps): 2 m-atoms, 4 n-atoms, 3 split terms
__device__ __forceinline__ void mma_step(uint32_t sb, const uint32_t* aoff,
                                         const uint32_t* boff, float acc[2][4][4],
                                         uint32_t ksb) {
    uint32_t ahi[2][4], alo[2][4], bhi[4][2], blo[4][2];
#pragma unroll
    for (int am = 0; am < 2; am++) {
        ldsm4t(ahi[am], sb + OFF_A_HI + aoff[am] + ksb);
        ldsm4t(alo[am], sb + OFF_A_LO + aoff[am] + ksb);
    }
#pragma unroll
    for (int an = 0; an < 4; an++) {
        ldsm2t(bhi[an], sb + OFF_B_HI + boff[an] + ksb);
        ldsm2t(blo[an], sb + OFF_B_LO + boff[an] + ksb);
    }
#pragma unroll
    for (int am = 0; am < 2; am++)
#pragma unroll
        for (int an = 0; an < 4; an++) {
            mma16816(acc[am][an], ahi[am], bhi[an]);
            mma16816(acc[am][an], ahi[am], blo[an]);
            mma16816(acc[am][an], alo[am], bhi[an]);
        }
}

// ---------------- prep: zero stats + split weights to bf16 hi/lo ----------------
__global__ void prep_kernel(const float* __restrict__ w0, const float* __restrict__ w1) {
    const int idx = blockIdx.x * 256 + threadIdx.x;  // grid 512 -> 131072
    if (idx < 256) { g_sum0[idx] = 0.f; g_sq0[idx] = 0.f; }
    if (idx < 128) { g_sum1[idx] = 0.f; g_sq1[idx] = 0.f; }
    if (idx < 512 * 256) {
        const float v = w0[(idx & 255) * 512 + (idx >> 8)];
        const __nv_bfloat16 h = __float2bfloat16(v);
        g_W0Thi[idx] = h;
        g_W0Tlo[idx] = __float2bfloat16(v - __bfloat162float(h));
    }
    if (idx < 256 * 128) {
        const float v = w1[(idx & 127) * 256 + (idx >> 7)];
        const __nv_bfloat16 h = __float2bfloat16(v);
        g_W1Thi[idx] = h;
        g_W1Tlo[idx] = __float2bfloat16(v - __bfloat162float(h));
    }
}

__device__ __forceinline__ uint32_t bf2u(__nv_bfloat16 a, __nv_bfloat16 b) {
    return (uint32_t)__bfloat16_as_ushort(a) | ((uint32_t)__bfloat16_as_ushort(b) << 16);
}

// split p1 [B][128][4096] -> [128][65536] bf16 hi/lo
__global__ void p1split_kernel(const float* __restrict__ p1) {
    const int idx4 = blockIdx.x * 256 + threadIdx.x;   // 2097152
    const int e = idx4 * 4;
    const int k = e >> 16, col = e & 65535;
    const int b = col >> 12, n = col & 4095;
    float4 v = *(const float4*)&p1[(size_t)b * 524288 + (size_t)k * 4096 + n];
    __nv_bfloat16 h0 = __float2bfloat16(v.x), h1 = __float2bfloat16(v.y);
    __nv_bfloat16 h2 = __float2bfloat16(v.z), h3 = __float2bfloat16(v.w);
    uint2 hi = make_uint2(bf2u(h0, h1), bf2u(h2, h3));
    uint2 lo = make_uint2(bf2u(__float2bfloat16(v.x - __bfloat162float(h0)),
                               __float2bfloat16(v.y - __bfloat162float(h1))),
                          bf2u(__float2bfloat16(v.z - __bfloat162float(h2)),
                               __float2bfloat16(v.w - __bfloat162float(h3))));
    *(uint2*)&g_P1hi[(size_t)k * 65536 + col] = hi;
    *(uint2*)&g_P1lo[(size_t)k * 65536 + col] = lo;
}

// split p2 [B][128][1024] -> [128][16384]
__global__ void p2split_kernel(const float* __restrict__ p2) {
    const int idx4 = blockIdx.x * 256 + threadIdx.x;   // 524288
    const int e = idx4 * 4;
    const int k = e >> 14, col = e & 16383;
    const int b = col >> 10, s = col & 1023;
    float4 v = *(const float4*)&p2[(size_t)b * 131072 + (size_t)k * 1024 + s];
    __nv_bfloat16 h0 = __float2bfloat16(v.x), h1 = __float2bfloat16(v.y);
    __nv_bfloat16 h2 = __float2bfloat16(v.z), h3 = __float2bfloat16(v.w);
    *(uint2*)&g_P2hi[(size_t)k * 16384 + col] = make_uint2(bf2u(h0, h1), bf2u(h2, h3));
    *(uint2*)&g_P2lo[(size_t)k * 16384 + col] =
        make_uint2(bf2u(__float2bfloat16(v.x - __bfloat162float(h0)),
                        __float2bfloat16(v.y - __bfloat162float(h1))),
                   bf2u(__float2bfloat16(v.z - __bfloat162float(h2)),
                        __float2bfloat16(v.w - __bfloat162float(h3))));
}

// h = relu(a0*Y + c0), split to bf16 hi/lo
__global__ void bnsplit_kernel() {
    const int idx4 = blockIdx.x * 256 + threadIdx.x;   // 4194304
    const int e = idx4 * 4;
    const int k = e >> 16, col = e & 65535;
    const float a = g_a0[k], c = g_c0[k];
    float4 v = *(const float4*)&g_Y[(size_t)k * 65536 + col];
    v.x = fmaxf(0.f, fmaf(a, v.x, c));
    v.y = fmaxf(0.f, fmaf(a, v.y, c));
    v.z = fmaxf(0.f, fmaf(a, v.z, c));
    v.w = fmaxf(0.f, fmaf(a, v.w, c));
    __nv_bfloat16 h0 = __float2bfloat16(v.x), h1 = __float2bfloat16(v.y);
    __nv_bfloat16 h2 = __float2bfloat16(v.z), h3 = __float2bfloat16(v.w);
    *(uint2*)&g_Hhi[(size_t)k * 65536 + col] = make_uint2(bf2u(h0, h1), bf2u(h2, h3));
    *(uint2*)&g_Hlo[(size_t)k * 65536 + col] =
        make_uint2(bf2u(__float2bfloat16(v.x - __bfloat162float(h0)),
                        __float2bfloat16(v.y - __bfloat162float(h1))),
                   bf2u(__float2bfloat16(v.z - __bfloat162float(h2)),
                        __float2bfloat16(v.w - __bfloat162float(h3))));
}

// ---------------- 3-NN search + interpolation weights ----------------
__global__ void knn_kernel(const float* __restrict__ xyz1,
                           const float* __restrict__ xyz2) {
    __shared__ float sx[SPTS], sy[SPTS], sz[SPTS], sn[SPTS];
    const int t = threadIdx.x;
    const int b = blockIdx.x >> 4;
    const int qbase = (blockIdx.x & 15) << 8;
    const float* base2 = xyz2 + (size_t)b * 3 * SPTS;
    for (int i = t; i < SPTS; i += 256) {
        float x = base2[i], y = base2[SPTS + i], z = base2[2 * SPTS + i];
        sx[i] = x; sy[i] = y; sz[i] = z; sn[i] = x * x + y * y + z * z;
    }
    __syncthreads();
    const int n = qbase + t;
    const float* base1 = xyz1 + (size_t)b * 3 * NPTS;
    const float qx = base1[n], qy = base1[NPTS + n], qz = base1[2 * NPTS + n];
    const float qn = qx * qx + qy * qy + qz * qz;
    float d0 = 3.4e38f, d1 = 3.4e38f, d2 = 3.4e38f;
    int i0 = 0, i1 = 0, i2 = 0;
#pragma unroll 4
    for (int s = 0; s < SPTS; s++) {
        float d = qn + sn[s] - 2.f * (qx * sx[s] + qy * sy[s] + qz * sz[s]);
        if (d < d2) {
            if (d < d1) {
                if (d < d0) { d2 = d1; i2 = i1; d1 = d0; i1 = i0; d0 = d; i0 = s; }
                else        { d2 = d1; i2 = i1; d1 = d;  i1 = s; }
            } else          { d2 = d;  i2 = s; }
        }
    }
    const float r0 = 1.f / (d0 + 1e-8f);
    const float r1 = 1.f / (d1 + 1e-8f);
    const float r2 = 1.f / (d2 + 1e-8f);
    const float inv = 1.f / (r0 + r1 + r2);
    const int col = b * NPTS + n;
    g_idx[col * 3 + 0] = i0; g_idx[col * 3 + 1] = i1; g_idx[col * 3 + 2] = i2;
    g_w[col * 3 + 0] = r0 * inv; g_w[col * 3 + 1] = r1 * inv; g_w[col * 3 + 2] = r2 * inv;
}

// Shared per-thread mma setup: 512 threads, 16 warps (wm 0..3 x wn 0..3)
#define MMA_SETUP() \
    const int t = threadIdx.x; \
    const int L = t & 31, w = t >> 5; \
    const int wm = w >> 2, wn = w & 3; \
    const uint32_t smemBase = (uint32_t)__cvta_generic_to_shared(sm); \
    const int lk = t >> 4, lg = t & 15; \
    const uint32_t dstoff = (uint32_t)(lk * 256 + ((lg ^ (lk & 7)) << 4)); \
    uint32_t aoff[2], boff[4]; \
    { \
        const int mtx = L >> 3; \
        const int kA = (L & 7) + ((mtx & 2) << 2); \
        const int mA = wm * 32 + ((mtx & 1) << 3); \
        _Pragma("unroll") \
        for (int am = 0; am < 2; am++) \
            aoff[am] = (uint32_t)(kA * 256 + ((((mA + am * 16) >> 3) ^ (kA & 7)) << 4)); \
        const int kB = L & 15; \
        _Pragma("unroll") \
        for (int an = 0; an < 4; an++) { \
            const int nB = wn * 32 + an * 8; \
            boff[an] = (uint32_t)(kB * 256 + (((nB >> 3) ^ (kB & 7)) << 4)); \
        } \
    } \
    float acc[2][4][4]; \
    _Pragma("unroll") \
    for (int am = 0; am < 2; am++) \
        _Pragma("unroll") \
        for (int an = 0; an < 4; an++) \
            _Pragma("unroll") \
            for (int d = 0; d < 4; d++) acc[am][an][d] = 0.f;

#define LOAD_STAGE(sbuf, kt) do { \
    const size_t ka = (size_t)((kt) * 32 + lk); \
    cp16((sbuf) + OFF_A_HI + dstoff, aHi + ka * A_LD); \
    cp16((sbuf) + OFF_A_LO + dstoff, aLo + ka * A_LD); \
    cp16((sbuf) + OFF_B_HI + dstoff, bHi + ka * B_LD); \
    cp16((sbuf) + OFF_B_LO + dstoff, bLo + ka * B_LD); \
    cp_commit(); } while (0)

#define MMA_MAINLOOP(NT) \
    LOAD_STAGE(smemBase, 0); \
    LOAD_STAGE(smemBase + STAGE, 1); \
    { \
        int ls = 2, cs = 0; \
        _Pragma("unroll 1") \
        for (int kt = 0; kt < (NT); kt++) { \
            cp_wait<1>(); \
            __syncthreads(); \
            if (kt + 2 < (NT)) { LOAD_STAGE(smemBase + ls * STAGE, kt + 2); } \
            else cp_commit(); \
            ls++; if (ls == 3) ls = 0; \
            const uint32_t sb = smemBase + cs * STAGE; \
            mma_step(sb, aoff, boff, acc, 0); \
            mma_step(sb, aoff, boff, acc, 4096); \
            cs++; if (cs == 3) cs = 0; \
        } \
    }

// write fragments to smem C tile [128][132] fp32 then sync
#define FRAGS_TO_CS() \
    __syncthreads(); \
    float* Cs = (float*)sm; \
    _Pragma("unroll") \
    for (int am = 0; am < 2; am++) \
        _Pragma("unroll") \
        for (int an = 0; an < 4; an++) { \
            const int m = wm * 32 + am * 16 + (L >> 2); \
            const int n = wn * 32 + an * 8 + ((L & 3) << 1); \
            Cs[m * 132 + n]           = acc[am][an][0]; \
            Cs[m * 132 + n + 1]       = acc[am][an][1]; \
            Cs[(m + 8) * 132 + n]     = acc[am][an][2]; \
            Cs[(m + 8) * 132 + n + 1] = acc[am][an][3]; \
        } \
    __syncthreads();

// ---------------- GEMM Z (mma): M=128/block (6 blocks), K=128, cols=16384 ----------------
__global__ __launch_bounds__(512) void gemmZ_mma() {
    extern __shared__ __align__(16) char sm[];
    MMA_SETUP();
    const int col0 = blockIdx.x * 128;
    const int kg = blockIdx.y >> 1;
    const int o0 = (blockIdx.y & 1) * 128;
    const int A_LD = 256, B_LD = 16384;
    const __nv_bfloat16* aHi = g_W0Thi + (size_t)(128 + kg * 128) * 256 + o0 + lg * 8;
    const __nv_bfloat16* aLo = g_W0Tlo + (size_t)(128 + kg * 128) * 256 + o0 + lg * 8;
    const __nv_bfloat16* bHi = g_P2hi + col0 + lg * 8;
    const __nv_bfloat16* bLo = g_P2lo + col0 + lg * 8;
    MMA_MAINLOOP(4);
    // direct fragment store: g_Z[(kg*J + col)*256 + o]
#pragma unroll
    for (int am = 0; am < 2; am++)
#pragma unroll
        for (int an = 0; an < 4; an++) {
            const int m = o0 + wm * 32 + am * 16 + (L >> 2);
            const int n = col0 + wn * 32 + an * 8 + ((L & 3) << 1);
            float* z0 = g_Z + ((size_t)(kg * JCOLS + n)) * 256 + m;
            float* z1 = z0 + 256;
            z0[0] = acc[am][an][0];
            z1[0] = acc[am][an][1];
            z0[8] = acc[am][an][2];
            z1[8] = acc[am][an][3];
        }
}

// ---------------- GEMM Y (mma): M=256 (2 blocks), K=128, cols=65536 ----------------
__global__ __launch_bounds__(512) void gemmY_mma(const float* __restrict__ bias0) {
    extern __shared__ __align__(16) char sm[];
    MMA_SETUP();
    const int col0 = blockIdx.x * 128;
    const int m0 = blockIdx.y * 128;
    const int A_LD = 256, B_LD = 65536;
    const __nv_bfloat16* aHi = g_W0Thi + m0 + lg * 8;
    const __nv_bfloat16* aLo = g_W0Tlo + m0 + lg * 8;
    const __nv_bfloat16* bHi = g_P1hi + col0 + lg * 8;
    const __nv_bfloat16* bLo = g_P1lo + col0 + lg * 8;
    MMA_MAINLOOP(4);
    FRAGS_TO_CS();

    const int tx = t & 15, ty = t >> 4;
    const int rowb = m0 + ty * 4;
    float a4[4][8];
#pragma unroll
    for (int i = 0; i < 4; i++) {
        float4 u0 = *(const float4*)&Cs[(ty * 4 + i) * 132 + tx * 8];
        float4 u1 = *(const float4*)&Cs[(ty * 4 + i) * 132 + tx * 8 + 4];
        a4[i][0] = u0.x; a4[i][1] = u0.y; a4[i][2] = u0.z; a4[i][3] = u0.w;
        a4[i][4] = u1.x; a4[i][5] = u1.y; a4[i][6] = u1.z; a4[i][7] = u1.w;
    }
    float bias[4];
#pragma unroll
    for (int i = 0; i < 4; i++) bias[i] = bias0[rowb + i];

#pragma unroll
    for (int j = 0; j < 8; j++) {
        const int col = col0 + tx * 8 + j;
        const int ia = g_idx[col * 3], ib = g_idx[col * 3 + 1], ic = g_idx[col * 3 + 2];
        const float wa = g_w[col * 3], wb = g_w[col * 3 + 1], wc = g_w[col * 3 + 2];
        const int jb = (col >> 12) << 10;
        float4 p0 = *(const float4*)(g_Z + ((size_t)(jb + ia)) * 256 + rowb);
        float4 q0 = *(const float4*)(g_Z + ((size_t)(JCOLS + jb + ib)) * 256 + rowb);
        float4 r0 = *(const float4*)(g_Z + ((size_t)(2 * JCOLS + jb + ic)) * 256 + rowb);
        a4[0][j] += bias[0] + wa * p0.x + wb * q0.x + wc * r0.x;
        a4[1][j] += bias[1] + wa * p0.y + wb * q0.y + wc * r0.y;
        a4[2][j] += bias[2] + wa * p0.z + wb * q0.z + wc * r0.z;
        a4[3][j] += bias[3] + wa * p0.w + wb * q0.w + wc * r0.w;
    }

    const int colT = col0 + tx * 8;
#pragma unroll
    for (int i = 0; i < 4; i++) {
        const int row = rowb + i;
        float* yp = g_Y + (size_t)row * COLS + colT;
        *(float4*)yp       = make_float4(a4[i][0], a4[i][1], a4[i][2], a4[i][3]);
        *(float4*)(yp + 4) = make_float4(a4[i][4], a4[i][5], a4[i][6], a4[i][7]);
        float s = 0.f, q = 0.f;
#pragma unroll
        for (int j = 0; j < 8; j++) { s += a4[i][j]; q += a4[i][j] * a4[i][j]; }
#pragma unroll
        for (int off = 8; off; off >>= 1) {
            s += __shfl_xor_sync(0xffffffffu, s, off);
            q += __shfl_xor_sync(0xffffffffu, q, off);
        }
        if ((t & 15) == 0) { atomicAdd(&g_sum0[row], s); atomicAdd(&g_sq0[row], q); }
    }
}

__global__ void finalize0(const float* __restrict__ gamma, const float* __restrict__ beta) {
    const int t = threadIdx.x;
    const float mean = g_sum0[t] * (1.f / COLS);
    const float var = g_sq0[t] * (1.f / COLS) - mean * mean;
    const float a = gamma[t] * rsqrtf(var + 1e-5f);
    g_a0[t] = a;
    g_c0[t] = beta[t] - mean * a;
}

// ---------------- GEMM O2 (mma): M=128, K=256, cols=65536 ----------------
__global__ __launch_bounds__(512) void gemmO2_mma(const float* __restrict__ bias1) {
    extern __shared__ __align__(16) char sm[];
    MMA_SETUP();
    const int col0 = blockIdx.x * 128;
    const int A_LD = 128, B_LD = 65536;
    const __nv_bfloat16* aHi = g_W1Thi + lg * 8;
    const __nv_bfloat16* aLo = g_W1Tlo + lg * 8;
    const __nv_bfloat16* bHi = g_Hhi + col0 + lg * 8;
    const __nv_bfloat16* bLo = g_Hlo + col0 + lg * 8;
    MMA_MAINLOOP(8);
    FRAGS_TO_CS();

    const int tx = t & 15, ty = t >> 4;
    const int rowb = ty * 4;
    const int colT = col0 + tx * 8;
#pragma unroll
    for (int i = 0; i < 4; i++) {
        const int row = rowb + i;
        const float bias = bias1[row];
        float a8[8];
        float4 u0 = *(const float4*)&Cs[row * 132 + tx * 8];
        float4 u1 = *(const float4*)&Cs[row * 132 + tx * 8 + 4];
        a8[0] = u0.x + bias; a8[1] = u0.y + bias; a8[2] = u0.z + bias; a8[3] = u0.w + bias;
        a8[4] = u1.x + bias; a8[5] = u1.y + bias; a8[6] = u1.z + bias; a8[7] = u1.w + bias;
        float* op = g_O2 + (size_t)row * COLS + colT;
        *(float4*)op       = make_float4(a8[0], a8[1], a8[2], a8[3]);
        *(float4*)(op + 4) = make_float4(a8[4], a8[5], a8[6], a8[7]);
        float s = 0.f, q = 0.f;
#pragma unroll
        for (int j = 0; j < 8; j++) { s += a8[j]; q += a8[j] * a8[j]; }
#pragma unroll
        for (int off = 8; off; off >>= 1) {
            s += __shfl_xor_sync(0xffffffffu, s, off);
            q += __shfl_xor_sync(0xffffffffu, q, off);
        }
        if ((t & 15) == 0) { atomicAdd(&g_sum1[row], s); atomicAdd(&g_sq1[row], q); }
    }
}

__global__ void finalize1(const float* __restrict__ gamma, const float* __restrict__ beta) {
    const int t = threadIdx.x;
    const float mean = g_sum1[t] * (1.f / COLS);
    const float var = g_sq1[t] * (1.f / COLS) - mean * mean;
    const float a = gamma[t] * rsqrtf(var + 1e-5f);
    g_a1[t] = a;
    g_c1[t] = beta[t] - mean * a;
}

// ---------------- BN2 + ReLU + transpose store ----------------
__global__ void bnout_kernel(float* __restrict__ out) {
    const int idx = blockIdx.x * 256 + threadIdx.x;
    const int e = idx * 4;
    const int row = e >> 16;
    const int col = e & 65535;
    const int b = col >> 12, n = col & 4095;
    float4 v = *(const float4*)&g_O2[(size_t)row * COLS + col];
    const float a = g_a1[row], c = g_c1[row];
    float4 w;
    w.x = fmaxf(0.f, fmaf(a, v.x, c));
    w.y = fmaxf(0.f, fmaf(a, v.y, c));
    w.z = fmaxf(0.f, fmaf(a, v.z, c));
    w.w = fmaxf(0.f, fmaf(a, v.w, c));
    *(float4*)&out[((size_t)(b * 128 + row)) * 4096 + n] = w;
}

extern "C" void kernel_launch(void* const* d_in, const int* in_sizes, int n_in,
                              void* d_out, int out_size) {
    const float* xyz1 = (const float*)d_in[0];
    const float* xyz2 = (const float*)d_in[1];
    const float* p1   = (const float*)d_in[2];
    const float* p2   = (const float*)d_in[3];
    const float* w0   = (const float*)d_in[4];
    const float* b0   = (const float*)d_in[5];
    const float* g0   = (const float*)d_in[6];
    const float* be0  = (const float*)d_in[7];
    const float* w1   = (const float*)d_in[8];
    const float* b1   = (const float*)d_in[9];
    const float* g1   = (const float*)d_in[10];
    const float* be1  = (const float*)d_in[11];
    float* out = (float*)d_out;

    cudaFuncSetAttribute(gemmZ_mma, cudaFuncAttributeMaxDynamicSharedMemorySize, SMEM_BYTES);
    cudaFuncSetAttribute(gemmY_mma, cudaFuncAttributeMaxDynamicSharedMemorySize, SMEM_BYTES);
    cudaFuncSetAttribute(gemmO2_mma, cudaFuncAttributeMaxDynamicSharedMemorySize, SMEM_BYTES);

    prep_kernel<<<512, 256>>>(w0, w1);
    knn_kernel<<<256, 256>>>(xyz1, xyz2);
    p1split_kernel<<<8192, 256>>>(p1);
    p2split_kernel<<<2048, 256>>>(p2);
    gemmZ_mma<<<dim3(JCOLS / 128, 6), 512, SMEM_BYTES>>>();
    gemmY_mma<<<dim3(COLS / 128, 2), 512, SMEM_BYTES>>>(b0);
    finalize0<<<1, 256>>>(g0, be0);
    bnsplit_kernel<<<16384, 256>>>();
    gemmO2_mma<<<dim3(COLS / 128, 1), 512, SMEM_BYTES>>>(b1);
    finalize1<<<1, 128>>>(g1, be1);
    bnout_kernel<<<(COLS * 128 / 4) / 256, 256>>>(out);
}

// round 7
// speedup vs baseline: 1.4229x; 1.0215x over previous
#include <cuda_runtime.h>
#include <cuda_bf16.h>
#include <cstdint>

#define NB    16
#define NPTS  4096
#define SPTS  1024
#define COLS  65536
#define JCOLS 16384

// fp32 scratch
__device__ __align__(16) float g_Z[3u * 16384u * 256u];   // Z[k][col][o] o-contig
__device__ __align__(16) float g_Y[256u * 65536u];
__device__ __align__(16) float g_O2[128u * 65536u];
// bf16 split weights
__device__ __align__(16) __nv_bfloat16 g_W0Thi[512 * 256], g_W0Tlo[512 * 256];   // [c][o]
__device__ __align__(16) __nv_bfloat16 g_W1Thi[256 * 128], g_W1Tlo[256 * 128];   // [c][o]
__device__ int   g_idx[65536 * 3];
__device__ float g_w[65536 * 3];
__device__ float g_sum0[256], g_sq0[256], g_a0[256], g_c0[256];
__device__ float g_sum1[128], g_sq1[128], g_a1[128], g_c1[128];

__device__ __forceinline__ void cp16(uint32_t dst, const void* src) {
    asm volatile("cp.async.ca.shared.global [%0], [%1], 16;\n" :: "r"(dst), "l"(src));
}
__device__ __forceinline__ void cp_commit() { asm volatile("cp.async.commit_group;\n"); }
template<int N> __device__ __forceinline__ void cp_wait() {
    asm volatile("cp.async.wait_group %0;\n" :: "n"(N));
}

__device__ __forceinline__ void ldsm4t(uint32_t* r, uint32_t addr) {
    asm volatile("ldmatrix.sync.aligned.m8n8.x4.trans.shared.b16 {%0,%1,%2,%3}, [%4];"
                 : "=r"(r[0]), "=r"(r[1]), "=r"(r[2]), "=r"(r[3]) : "r"(addr));
}
__device__ __forceinline__ void ldsm2t(uint32_t* r, uint32_t addr) {
    asm volatile("ldmatrix.sync.aligned.m8n8.x2.trans.shared.b16 {%0,%1}, [%2];"
                 : "=r"(r[0]), "=r"(r[1]) : "r"(addr));
}
__device__ __forceinline__ void mma16816(float* d, const uint32_t* a, const uint32_t* b) {
    asm volatile("mma.sync.aligned.m16n8k16.row.col.f32.bf16.bf16.f32 "
                 "{%0,%1,%2,%3}, {%4,%5,%6,%7}, {%8,%9}, {%0,%1,%2,%3};"
                 : "+f"(d[0]), "+f"(d[1]), "+f"(d[2]), "+f"(d[3])
                 : "r"(a[0]), "r"(a[1]), "r"(a[2]), "r"(a[3]), "r"(b[0]), "r"(b[1]));
}
__device__ __forceinline__ uint32_t bf2u(__nv_bfloat16 a, __nv_bfloat16 b) {
    return (uint32_t)__bfloat16_as_ushort(a) | ((uint32_t)__bfloat16_as_ushort(b) << 16);
}

// smem layout (bytes):
//   stage s in {0,1,2}: A_hi 8K | A_lo 8K | B_f32 16K   (STAGE=32K)
//   conv (shared single buffer): B_hi 8K | B_lo 8K at CONV
#define OFF_A_HI 0
#define OFF_A_LO 8192
#define OFF_B_F32 16384
#define STAGE    32768
#define CONV     98304
#define SMEM_BYTES 114688

// one k16 compute step: 2 m-atoms x 4 n-atoms, 3 split terms
__device__ __forceinline__ void mma_step(uint32_t sbA, uint32_t sbB, const uint32_t* aoff,
                                         const uint32_t* boff, float acc[2][4][4],
                                         uint32_t ksb) {
    uint32_t ahi[2][4], alo[2][4], bhi[4][2], blo[4][2];
#pragma unroll
    for (int am = 0; am < 2; am++) {
        ldsm4t(ahi[am], sbA + OFF_A_HI + aoff[am] + ksb);
        ldsm4t(alo[am], sbA + OFF_A_LO + aoff[am] + ksb);
    }
#pragma unroll
    for (int an = 0; an < 4; an++) {
        ldsm2t(bhi[an], sbB + boff[an] + ksb);
        ldsm2t(blo[an], sbB + 8192 + boff[an] + ksb);
    }
#pragma unroll
    for (int am = 0; am < 2; am++)
#pragma unroll
        for (int an = 0; an < 4; an++) {
            mma16816(acc[am][an], ahi[am], bhi[an]);
            mma16816(acc[am][an], ahi[am], blo[an]);
            mma16816(acc[am][an], alo[am], bhi[an]);
        }
}

// Full pipelined mainloop: A pre-split bf16 hi/lo (global), B fp32 (global) converted
// in-smem per stage (optionally BN+ReLU first). NT k-tiles of 32.
template<int A_LD, int B_LD, int NT, bool BN>
__device__ __forceinline__ void mma_main(char* sm,
                                         const __nv_bfloat16* aHi, const __nv_bfloat16* aLo,
                                         const float* bF,
                                         const float* bnA, const float* bnC,
                                         float acc[2][4][4]) {
    const int t = threadIdx.x;
    const int L = t & 31, w = t >> 5;
    const int wm = w >> 2, wn = w & 3;
    const uint32_t smemBase = (uint32_t)__cvta_generic_to_shared(sm);
    const int lk = t >> 4, lg = t & 15;
    const uint32_t dstA = (uint32_t)(lk * 256 + ((lg ^ (lk & 7)) << 4));
    const uint32_t dstB = (uint32_t)(lk * 512 + lg * 32);

    uint32_t aoff[2], boff[4];
    {
        const int mtx = L >> 3;
        const int kA = (L & 7) + ((mtx & 2) << 2);
        const int mA = wm * 32 + ((mtx & 1) << 3);
#pragma unroll
        for (int am = 0; am < 2; am++)
            aoff[am] = (uint32_t)(kA * 256 + ((((mA + am * 16) >> 3) ^ (kA & 7)) << 4));
        const int kB = L & 15;
#pragma unroll
        for (int an = 0; an < 4; an++) {
            const int nB = wn * 32 + an * 8;
            boff[an] = (uint32_t)(kB * 256 + (((nB >> 3) ^ (kB & 7)) << 4));
        }
    }
#pragma unroll
    for (int am = 0; am < 2; am++)
#pragma unroll
        for (int an = 0; an < 4; an++)
#pragma unroll
            for (int d = 0; d < 4; d++) acc[am][an][d] = 0.f;

    const __nv_bfloat16* aH = aHi + lg * 8;
    const __nv_bfloat16* aL = aLo + lg * 8;
    const float* bP = bF + lg * 8;

#define LOAD_ST(buf, kt2) do { \
        const size_t ka = (size_t)((kt2) * 32 + lk); \
        cp16((buf) + OFF_A_HI + dstA, aH + ka * A_LD); \
        cp16((buf) + OFF_A_LO + dstA, aL + ka * A_LD); \
        cp16((buf) + OFF_B_F32 + dstB, bP + ka * B_LD); \
        cp16((buf) + OFF_B_F32 + dstB + 16, bP + ka * B_LD + 4); \
        cp_commit(); } while (0)

    LOAD_ST(smemBase, 0);
    LOAD_ST(smemBase + STAGE, 1);

    int ls = 2, cs = 0;
#pragma unroll 1
    for (int kt = 0; kt < NT; kt++) {
        cp_wait<1>();
        __syncthreads();            // stage kt ready; also guards conv reuse
        if (kt + 2 < NT) { LOAD_ST(smemBase + ls * STAGE, kt + 2); }
        else cp_commit();
        ls++; if (ls == 3) ls = 0;

        // convert B fp32 stage -> bf16 hi/lo (swizzled), optional BN+ReLU
        {
            const char* bsp = sm + cs * STAGE + OFF_B_F32 + lk * 512 + lg * 32;
            float4 u0 = *(const float4*)bsp;
            float4 u1 = *(const float4*)(bsp + 16);
            if (BN) {
                const int kabs = kt * 32 + lk;
                const float a = bnA[kabs], c = bnC[kabs];
                u0.x = fmaxf(0.f, fmaf(a, u0.x, c));
                u0.y = fmaxf(0.f, fmaf(a, u0.y, c));
                u0.z = fmaxf(0.f, fmaf(a, u0.z, c));
                u0.w = fmaxf(0.f, fmaf(a, u0.w, c));
                u1.x = fmaxf(0.f, fmaf(a, u1.x, c));
                u1.y = fmaxf(0.f, fmaf(a, u1.y, c));
                u1.z = fmaxf(0.f, fmaf(a, u1.z, c));
                u1.w = fmaxf(0.f, fmaf(a, u1.w, c));
            }
            const __nv_bfloat16 h0 = __float2bfloat16(u0.x), h1 = __float2bfloat16(u0.y);
            const __nv_bfloat16 h2 = __float2bfloat16(u0.z), h3 = __float2bfloat16(u0.w);
            const __nv_bfloat16 h4 = __float2bfloat16(u1.x), h5 = __float2bfloat16(u1.y);
            const __nv_bfloat16 h6 = __float2bfloat16(u1.z), h7 = __float2bfloat16(u1.w);
            uint4 hi = make_uint4(bf2u(h0, h1), bf2u(h2, h3), bf2u(h4, h5), bf2u(h6, h7));
            uint4 lo = make_uint4(
                bf2u(__float2bfloat16(u0.x - __bfloat162float(h0)),
                     __float2bfloat16(u0.y - __bfloat162float(h1))),
                bf2u(__float2bfloat16(u0.z - __bfloat162float(h2)),
                     __float2bfloat16(u0.w - __bfloat162float(h3))),
                bf2u(__float2bfloat16(u1.x - __bfloat162float(h4)),
                     __float2bfloat16(u1.y - __bfloat162float(h5))),
                bf2u(__float2bfloat16(u1.z - __bfloat162float(h6)),
                     __float2bfloat16(u1.w - __bfloat162float(h7))));
            char* cd = sm + CONV + lk * 256 + ((lg ^ (lk & 7)) << 4);
            *(uint4*)cd = hi;
            *(uint4*)(cd + 8192) = lo;
        }
        __syncthreads();            // converted tile visible

        const uint32_t sbA = smemBase + cs * STAGE;
        const uint32_t sbB = smemBase + CONV;
        mma_step(sbA, sbB, aoff, boff, acc, 0);
        mma_step(sbA, sbB, aoff, boff, acc, 4096);
        cs++; if (cs == 3) cs = 0;
    }
#undef LOAD_ST
}

// ---------------- prep: zero stats + split weights to bf16 hi/lo ----------------
__global__ void prep_kernel(const float* __restrict__ w0, const float* __restrict__ w1) {
    const int idx = blockIdx.x * 256 + threadIdx.x;  // grid 512
    if (idx < 256) { g_sum0[idx] = 0.f; g_sq0[idx] = 0.f; }
    if (idx < 128) { g_sum1[idx] = 0.f; g_sq1[idx] = 0.f; }
    if (idx < 512 * 256) {
        const float v = w0[(idx & 255) * 512 + (idx >> 8)];
        const __nv_bfloat16 h = __float2bfloat16(v);
        g_W0Thi[idx] = h;
        g_W0Tlo[idx] = __float2bfloat16(v - __bfloat162float(h));
    }
    if (idx < 256 * 128) {
        const float v = w1[(idx & 127) * 256 + (idx >> 7)];
        const __nv_bfloat16 h = __float2bfloat16(v);
        g_W1Thi[idx] = h;
        g_W1Tlo[idx] = __float2bfloat16(v - __bfloat162float(h));
    }
}

// ---------------- 3-NN search + interpolation weights ----------------
__global__ void knn_kernel(const float* __restrict__ xyz1,
                           const float* __restrict__ xyz2) {
    __shared__ float sx[SPTS], sy[SPTS], sz[SPTS], sn[SPTS];
    const int t = threadIdx.x;
    const int b = blockIdx.x >> 4;
    const int qbase = (blockIdx.x & 15) << 8;
    const float* base2 = xyz2 + (size_t)b * 3 * SPTS;
    for (int i = t; i < SPTS; i += 256) {
        float x = base2[i], y = base2[SPTS + i], z = base2[2 * SPTS + i];
        sx[i] = x; sy[i] = y; sz[i] = z; sn[i] = x * x + y * y + z * z;
    }
    __syncthreads();
    const int n = qbase + t;
    const float* base1 = xyz1 + (size_t)b * 3 * NPTS;
    const float qx = base1[n], qy = base1[NPTS + n], qz = base1[2 * NPTS + n];
    const float qn = qx * qx + qy * qy + qz * qz;
    float d0 = 3.4e38f, d1 = 3.4e38f, d2 = 3.4e38f;
    int i0 = 0, i1 = 0, i2 = 0;
#pragma unroll 4
    for (int s = 0; s < SPTS; s++) {
        float d = qn + sn[s] - 2.f * (qx * sx[s] + qy * sy[s] + qz * sz[s]);
        if (d < d2) {
            if (d < d1) {
                if (d < d0) { d2 = d1; i2 = i1; d1 = d0; i1 = i0; d0 = d; i0 = s; }
                else        { d2 = d1; i2 = i1; d1 = d;  i1 = s; }
            } else          { d2 = d;  i2 = s; }
        }
    }
    const float r0 = 1.f / (d0 + 1e-8f);
    const float r1 = 1.f / (d1 + 1e-8f);
    const float r2 = 1.f / (d2 + 1e-8f);
    const float inv = 1.f / (r0 + r1 + r2);
    const int col = b * NPTS + n;
    g_idx[col * 3 + 0] = i0; g_idx[col * 3 + 1] = i1; g_idx[col * 3 + 2] = i2;
    g_w[col * 3 + 0] = r0 * inv; g_w[col * 3 + 1] = r1 * inv; g_w[col * 3 + 2] = r2 * inv;
}

// ---------------- GEMM Z: M=128/block (6 y-blocks), K=128, cols=16384 ----------------
__global__ __launch_bounds__(512) void gemmZ_mma(const float* __restrict__ p2) {
    extern __shared__ __align__(16) char sm[];
    const int t = threadIdx.x;
    const int L = t & 31, w = t >> 5;
    const int wm = w >> 2, wn = w & 3;
    const int col0 = blockIdx.x * 128;
    const int kg = blockIdx.y >> 1;
    const int o0 = (blockIdx.y & 1) * 128;
    const int bb = col0 >> 10, sOff = col0 & 1023;

    float acc[2][4][4];
    mma_main<256, 1024, 4, false>(sm,
        g_W0Thi + (size_t)(128 + kg * 128) * 256 + o0,
        g_W0Tlo + (size_t)(128 + kg * 128) * 256 + o0,
        p2 + (size_t)bb * 131072 + sOff,
        nullptr, nullptr, acc);

#pragma unroll
    for (int am = 0; am < 2; am++)
#pragma unroll
        for (int an = 0; an < 4; an++) {
            const int m = o0 + wm * 32 + am * 16 + (L >> 2);
            const int n = col0 + wn * 32 + an * 8 + ((L & 3) << 1);
            float* z0 = g_Z + ((size_t)(kg * JCOLS + n)) * 256 + m;
            float* z1 = z0 + 256;
            z0[0] = acc[am][an][0];
            z1[0] = acc[am][an][1];
            z0[8] = acc[am][an][2];
            z1[8] = acc[am][an][3];
        }
}

// write fragments to smem C tile [128][132] fp32 then sync
#define FRAGS_TO_CS() \
    __syncthreads(); \
    float* Cs = (float*)sm; \
    _Pragma("unroll") \
    for (int am = 0; am < 2; am++) \
        _Pragma("unroll") \
        for (int an = 0; an < 4; an++) { \
            const int m = wm * 32 + am * 16 + (L >> 2); \
            const int n = wn * 32 + an * 8 + ((L & 3) << 1); \
            Cs[m * 132 + n]           = acc[am][an][0]; \
            Cs[m * 132 + n + 1]       = acc[am][an][1]; \
            Cs[(m + 8) * 132 + n]     = acc[am][an][2]; \
            Cs[(m + 8) * 132 + n + 1] = acc[am][an][3]; \
        } \
    __syncthreads();

// ---------------- GEMM Y: M=256 (2 y-blocks), K=128, cols=65536 ----------------
__global__ __launch_bounds__(512) void gemmY_mma(const float* __restrict__ p1,
                                                 const float* __restrict__ bias0) {
    extern __shared__ __align__(16) char sm[];
    const int t = threadIdx.x;
    const int L = t & 31, w = t >> 5;
    const int wm = w >> 2, wn = w & 3;
    const int col0 = blockIdx.x * 128;
    const int m0 = blockIdx.y * 128;
    const int bb = col0 >> 12, nOff = col0 & 4095;

    float acc[2][4][4];
    mma_main<256, 4096, 4, false>(sm,
        g_W0Thi + m0, g_W0Tlo + m0,
        p1 + (size_t)bb * 524288 + nOff,
        nullptr, nullptr, acc);

    FRAGS_TO_CS();

    const int tx = t & 15, ty = t >> 4;
    const int rowb = m0 + ty * 4;
    float a4[4][8];
#pragma unroll
    for (int i = 0; i < 4; i++) {
        float4 u0 = *(const float4*)&Cs[(ty * 4 + i) * 132 + tx * 8];
        float4 u1 = *(const float4*)&Cs[(ty * 4 + i) * 132 + tx * 8 + 4];
        a4[i][0] = u0.x; a4[i][1] = u0.y; a4[i][2] = u0.z; a4[i][3] = u0.w;
        a4[i][4] = u1.x; a4[i][5] = u1.y; a4[i][6] = u1.z; a4[i][7] = u1.w;
    }
    float bias[4];
#pragma unroll
    for (int i = 0; i < 4; i++) bias[i] = bias0[rowb + i];

#pragma unroll
    for (int j = 0; j < 8; j++) {
        const int col = col0 + tx * 8 + j;
        const int ia = g_idx[col * 3], ib = g_idx[col * 3 + 1], ic = g_idx[col * 3 + 2];
        const float wa = g_w[col * 3], wb = g_w[col * 3 + 1], wc = g_w[col * 3 + 2];
        const int jb = (col >> 12) << 10;
        float4 p0 = *(const float4*)(g_Z + ((size_t)(jb + ia)) * 256 + rowb);
        float4 q0 = *(const float4*)(g_Z + ((size_t)(JCOLS + jb + ib)) * 256 + rowb);
        float4 r0 = *(const float4*)(g_Z + ((size_t)(2 * JCOLS + jb + ic)) * 256 + rowb);
        a4[0][j] += bias[0] + wa * p0.x + wb * q0.x + wc * r0.x;
        a4[1][j] += bias[1] + wa * p0.y + wb * q0.y + wc * r0.y;
        a4[2][j] += bias[2] + wa * p0.z + wb * q0.z + wc * r0.z;
        a4[3][j] += bias[3] + wa * p0.w + wb * q0.w + wc * r0.w;
    }

    const int colT = col0 + tx * 8;
#pragma unroll
    for (int i = 0; i < 4; i++) {
        const int row = rowb + i;
        float* yp = g_Y + (size_t)row * COLS + colT;
        *(float4*)yp       = make_float4(a4[i][0], a4[i][1], a4[i][2], a4[i][3]);
        *(float4*)(yp + 4) = make_float4(a4[i][4], a4[i][5], a4[i][6], a4[i][7]);
        float s = 0.f, q = 0.f;
#pragma unroll
        for (int j = 0; j < 8; j++) { s += a4[i][j]; q += a4[i][j] * a4[i][j]; }
#pragma unroll
        for (int off = 8; off; off >>= 1) {
            s += __shfl_xor_sync(0xffffffffu, s, off);
            q += __shfl_xor_sync(0xffffffffu, q, off);
        }
        if ((t & 15) == 0) { atomicAdd(&g_sum0[row], s); atomicAdd(&g_sq0[row], q); }
    }
}

__global__ void finalize0(const float* __restrict__ gamma, const float* __restrict__ beta) {
    const int t = threadIdx.x;
    const float mean = g_sum0[t] * (1.f / COLS);
    const float var = g_sq0[t] * (1.f / COLS) - mean * mean;
    const float a = gamma[t] * rsqrtf(var + 1e-5f);
    g_a0[t] = a;
    g_c0[t] = beta[t] - mean * a;
}

// ---------------- GEMM O2: M=128, K=256, cols=65536; BN0+ReLU fused on B ----------------
__global__ __launch_bounds__(512) void gemmO2_mma(const float* __restrict__ bias1) {
    extern __shared__ __align__(16) char sm[];
    __shared__ float s_a0[256], s_c0[256];
    const int t = threadIdx.x;
    const int L = t & 31, w = t >> 5;
    const int wm = w >> 2, wn = w & 3;
    const int col0 = blockIdx.x * 128;
    if (t < 256) { s_a0[t] = g_a0[t]; s_c0[t] = g_c0[t]; }

    float acc[2][4][4];
    mma_main<128, 65536, 8, true>(sm,
        g_W1Thi, g_W1Tlo,
        g_Y + col0,
        s_a0, s_c0, acc);

    FRAGS_TO_CS();

    const int tx = t & 15, ty = t >> 4;
    const int rowb = ty * 4;
    const int colT = col0 + tx * 8;
#pragma unroll
    for (int i = 0; i < 4; i++) {
        const int row = rowb + i;
        const float bias = bias1[row];
        float a8[8];
        float4 u0 = *(const float4*)&Cs[row * 132 + tx * 8];
        float4 u1 = *(const float4*)&Cs[row * 132 + tx * 8 + 4];
        a8[0] = u0.x + bias; a8[1] = u0.y + bias; a8[2] = u0.z + bias; a8[3] = u0.w + bias;
        a8[4] = u1.x + bias; a8[5] = u1.y + bias; a8[6] = u1.z + bias; a8[7] = u1.w + bias;
        float* op = g_O2 + (size_t)row * COLS + colT;
        *(float4*)op       = make_float4(a8[0], a8[1], a8[2], a8[3]);
        *(float4*)(op + 4) = make_float4(a8[4], a8[5], a8[6], a8[7]);
        float s = 0.f, q = 0.f;
#pragma unroll
        for (int j = 0; j < 8; j++) { s += a8[j]; q += a8[j] * a8[j]; }
#pragma unroll
        for (int off = 8; off; off >>= 1) {
            s += __shfl_xor_sync(0xffffffffu, s, off);
            q += __shfl_xor_sync(0xffffffffu, q, off);
        }
        if ((t & 15) == 0) { atomicAdd(&g_sum1[row], s); atomicAdd(&g_sq1[row], q); }
    }
}

__global__ void finalize1(const float* __restrict__ gamma, const float* __restrict__ beta) {
    const int t = threadIdx.x;
    const float mean = g_sum1[t] * (1.f / COLS);
    const float var = g_sq1[t] * (1.f / COLS) - mean * mean;
    const float a = gamma[t] * rsqrtf(var + 1e-5f);
    g_a1[t] = a;
    g_c1[t] = beta[t] - mean * a;
}

// ---------------- BN2 + ReLU + transpose store ----------------
__global__ void bnout_kernel(float* __restrict__ out) {
    const int idx = blockIdx.x * 256 + threadIdx.x;
    const int e = idx * 4;
    const int row = e >> 16;
    const int col = e & 65535;
    const int b = col >> 12, n = col & 4095;
    float4 v = *(const float4*)&g_O2[(size_t)row * COLS + col];
    const float a = g_a1[row], c = g_c1[row];
    float4 w;
    w.x = fmaxf(0.f, fmaf(a, v.x, c));
    w.y = fmaxf(0.f, fmaf(a, v.y, c));
    w.z = fmaxf(0.f, fmaf(a, v.z, c));
    w.w = fmaxf(0.f, fmaf(a, v.w, c));
    *(float4*)&out[((size_t)(b * 128 + row)) * 4096 + n] = w;
}

extern "C" void kernel_launch(void* const* d_in, const int* in_sizes, int n_in,
                              void* d_out, int out_size) {
    const float* xyz1 = (const float*)d_in[0];
    const float* xyz2 = (const float*)d_in[1];
    const float* p1   = (const float*)d_in[2];
    const float* p2   = (const float*)d_in[3];
    const float* w0   = (const float*)d_in[4];
    const float* b0   = (const float*)d_in[5];
    const float* g0   = (const float*)d_in[6];
    const float* be0  = (const float*)d_in[7];
    const float* w1   = (const float*)d_in[8];
    const float* b1   = (const float*)d_in[9];
    const float* g1   = (const float*)d_in[10];
    const float* be1  = (const float*)d_in[11];
    float* out = (float*)d_out;

    cudaFuncSetAttribute(gemmZ_mma, cudaFuncAttributeMaxDynamicSharedMemorySize, SMEM_BYTES);
    cudaFuncSetAttribute(gemmY_mma, cudaFuncAttributeMaxDynamicSharedMemorySize, SMEM_BYTES);
    cudaFuncSetAttribute(gemmO2_mma, cudaFuncAttributeMaxDynamicSharedMemorySize, SMEM_BYTES);

    prep_kernel<<<512, 256>>>(w0, w1);                              // 1
    knn_kernel<<<256, 256>>>(xyz1, xyz2);                           // 2
    gemmZ_mma<<<dim3(JCOLS / 128, 6), 512, SMEM_BYTES>>>(p2);       // 3
    gemmY_mma<<<dim3(COLS / 128, 2), 512, SMEM_BYTES>>>(p1, b0);    // 4
    finalize0<<<1, 256>>>(g0, be0);                                 // 5
    gemmO2_mma<<<COLS / 128, 512, SMEM_BYTES>>>(b1);                // 6 (profiled)
    finalize1<<<1, 128>>>(g1, be1);                                 // 7
    bnout_kernel<<<(COLS * 128 / 4) / 256, 256>>>(out);             // 8
}